// round 3
// baseline (speedup 1.0000x reference)
#include <cuda_runtime.h>
#include <cuda_bf16.h>
#include <cuda_fp8.h>
#include <cstdint>

static constexpr int Mdim = 16384;
static constexpr int Kdim = 4096;
static constexpr int Ndim = 4096;
static constexpr float FP8MAX = 448.0f;

// ---------------- scratch (device globals; no dynamic allocation) -------------
__device__ __align__(16) unsigned char g_xq[(size_t)Mdim * Kdim];  // x quantized, fp8 e4m3
__device__ __align__(16) unsigned char g_wq[(size_t)Ndim * Kdim];  // w^T quantized, fp8 e4m3
__device__ unsigned int g_absmax[2];
__device__ float g_scales[3];  // sx, sw, 1/(sx*sw)

// ---------------- phase 1: absmax reductions ---------------------------------
__global__ void k_reset() {
    g_absmax[0] = 0u;
    g_absmax[1] = 0u;
}

__global__ void k_absmax(const float4* __restrict__ p, int n4, int which) {
    float m = 0.f;
    for (int i = blockIdx.x * blockDim.x + threadIdx.x; i < n4; i += gridDim.x * blockDim.x) {
        float4 v = p[i];
        m = fmaxf(m, fmaxf(fmaxf(fabsf(v.x), fabsf(v.y)), fmaxf(fabsf(v.z), fabsf(v.w))));
    }
#pragma unroll
    for (int o = 16; o > 0; o >>= 1) m = fmaxf(m, __shfl_xor_sync(0xffffffffu, m, o));
    __shared__ float red[8];
    if ((threadIdx.x & 31) == 0) red[threadIdx.x >> 5] = m;
    __syncthreads();
    if (threadIdx.x == 0) {
        float mm = red[0];
#pragma unroll
        for (int i = 1; i < 8; i++) mm = fmaxf(mm, red[i]);
        atomicMax(&g_absmax[which], __float_as_uint(mm));
    }
}

__global__ void k_scales() {
    float ax = __uint_as_float(g_absmax[0]);
    float aw = __uint_as_float(g_absmax[1]);
    float sx = FP8MAX / ax;
    float sw = FP8MAX / aw;
    g_scales[0] = sx;
    g_scales[1] = sw;
    g_scales[2] = 1.0f / (sx * sw);
}

// ---------------- phase 2: quantize to fp8 e4m3 bytes ------------------------
__device__ __forceinline__ unsigned int quant8(float v, float s) {
    float q = fminf(fmaxf(v * s, -FP8MAX), FP8MAX);
    __nv_fp8_e4m3 f8(q);  // RN + satfinite, matches jnp float8_e4m3fn cast
    return (unsigned int)*reinterpret_cast<unsigned char*>(&f8);
}

__global__ void k_quant_x(const float4* __restrict__ x, int n16) {
    const float s = g_scales[0];
    uint4* __restrict__ out = reinterpret_cast<uint4*>(g_xq);
    for (int i = blockIdx.x * blockDim.x + threadIdx.x; i < n16; i += gridDim.x * blockDim.x) {
        unsigned int r[4];
#pragma unroll
        for (int j = 0; j < 4; j++) {
            float4 a = x[4 * i + j];
            r[j] = quant8(a.x, s) | (quant8(a.y, s) << 8) |
                   (quant8(a.z, s) << 16) | (quant8(a.w, s) << 24);
        }
        out[i] = make_uint4(r[0], r[1], r[2], r[3]);
    }
}

// w[K,N] -> g_wq[N,K] fp8 (quantize + transpose via smem tile)
__global__ void k_quant_wt(const float* __restrict__ w) {
    __shared__ float tile[32][33];  // [k][n]
    const float s = g_scales[1];
    int n0 = blockIdx.x * 32, k0 = blockIdx.y * 32;
    int tx = threadIdx.x, ty = threadIdx.y;
#pragma unroll
    for (int j = ty; j < 32; j += 8)
        tile[j][tx] = w[(size_t)(k0 + j) * Ndim + n0 + tx];
    __syncthreads();
    // 256 threads: each packs 4 consecutive k-bytes for one n-row
    int t = ty * 32 + tx;
    int n = t >> 3, kq = (t & 7) * 4;
    unsigned int r = quant8(tile[kq][n], s) | (quant8(tile[kq + 1][n], s) << 8) |
                     (quant8(tile[kq + 2][n], s) << 16) | (quant8(tile[kq + 3][n], s) << 24);
    *reinterpret_cast<unsigned int*>(g_wq + (size_t)(n0 + n) * Kdim + k0 + kq) = r;
}

// ---------------- phase 3: fp8 mma.sync GEMM ---------------------------------
// CTA tile 128x128, BK=128 fp8 (128B rows), 8 warps (2x4) each 64x32,
// 3-stage cp.async pipeline, XOR-swizzled smem, fp32 register accumulators.
static constexpr int BM = 128, BN = 128, BK = 128;
static constexpr int ROWB = BK;                     // 128 bytes per smem row
static constexpr int ATILE = BM * ROWB;             // 16384
static constexpr int STAGE = 2 * ATILE;             // A + B = 32768
static constexpr int NSTAGE = 3;
static constexpr int SMEM_TOTAL = NSTAGE * STAGE;   // 98304

#define CPA16(dst, src) \
    asm volatile("cp.async.cg.shared.global [%0], [%1], 16;" :: "r"(dst), "l"(src))
#define LDSM4(r0, r1, r2, r3, addr) \
    asm volatile("ldmatrix.sync.aligned.m8n8.x4.shared.b16 {%0,%1,%2,%3}, [%4];" \
                 : "=r"(r0), "=r"(r1), "=r"(r2), "=r"(r3) : "r"(addr))

__device__ __forceinline__ void mma_fp8(float* c, const uint32_t* a, const uint32_t* b) {
    asm volatile(
        "mma.sync.aligned.m16n8k32.row.col.f32.e4m3.e4m3.f32 "
        "{%0,%1,%2,%3}, {%4,%5,%6,%7}, {%8,%9}, {%0,%1,%2,%3};"
        : "+f"(c[0]), "+f"(c[1]), "+f"(c[2]), "+f"(c[3])
        : "r"(a[0]), "r"(a[1]), "r"(a[2]), "r"(a[3]), "r"(b[0]), "r"(b[1]));
}

__global__ void __launch_bounds__(256, 2) k_gemm(float* __restrict__ out) {
    extern __shared__ char smem[];
    const uint32_t sb = (uint32_t)__cvta_generic_to_shared(smem);
    const int tid = threadIdx.x, wid = tid >> 5, lid = tid & 31;
    const int warp_m = wid >> 2, warp_n = wid & 3;
    const int n0 = blockIdx.x * BN, m0 = blockIdx.y * BM;
    const float inv = g_scales[2];

    const char* Ag = (const char*)g_xq + (size_t)m0 * Kdim;
    const char* Bg = (const char*)g_wq + (size_t)n0 * Kdim;

    const int lr = tid >> 3;  // 0..31 base row
    const int lc = tid & 7;   // 16B chunk within 128B row

    auto load_stage = [&](int kc, int st) {
        const uint32_t ab = sb + st * STAGE;
        const uint32_t bb = ab + ATILE;
        const size_t kbyte = (size_t)kc * ROWB;
#pragma unroll
        for (int i = 0; i < 4; i++) {
            int r = lr + i * 32;
            uint32_t so = (uint32_t)(r * ROWB) + ((uint32_t)(lc ^ (r & 7)) << 4);
            CPA16(ab + so, Ag + (size_t)r * Kdim + kbyte + lc * 16);
            CPA16(bb + so, Bg + (size_t)r * Kdim + kbyte + lc * 16);
        }
    };

    // ldmatrix per-thread row/chunk layout (byte-identical to bf16-k16 case)
    int arow[4], brow[2];
#pragma unroll
    for (int mt = 0; mt < 4; mt++) arow[mt] = warp_m * 64 + mt * 16 + (lid & 15);
#pragma unroll
    for (int bt = 0; bt < 2; bt++) brow[bt] = warp_n * 32 + bt * 16 + ((lid >> 4) << 3) + (lid & 7);
    const int a_c = lid >> 4;        // low/high 16B of the 32B k-slice
    const int b_c = (lid >> 3) & 1;

    float acc[4][4][4];
#pragma unroll
    for (int mt = 0; mt < 4; mt++)
#pragma unroll
        for (int nt = 0; nt < 4; nt++)
#pragma unroll
            for (int i = 0; i < 4; i++) acc[mt][nt][i] = 0.f;

    load_stage(0, 0);
    asm volatile("cp.async.commit_group;");
    load_stage(1, 1);
    asm volatile("cp.async.commit_group;");

    const int NC = Kdim / BK;  // 32
    for (int kc = 0; kc < NC; kc++) {
        asm volatile("cp.async.wait_group 1;");
        __syncthreads();
        const int st = kc % NSTAGE;
        const uint32_t Asm = sb + st * STAGE;
        const uint32_t Bsm = Asm + ATILE;

#pragma unroll
        for (int ks = 0; ks < 4; ks++) {  // 4 x k32 per 128B row
            uint32_t afr[4][4], bfr[4][2];
#pragma unroll
            for (int mt = 0; mt < 4; mt++) {
                int cc = ks * 2 + a_c;
                uint32_t ad = Asm + (uint32_t)(arow[mt] * ROWB) +
                              ((uint32_t)(cc ^ (arow[mt] & 7)) << 4);
                LDSM4(afr[mt][0], afr[mt][1], afr[mt][2], afr[mt][3], ad);
            }
#pragma unroll
            for (int bt = 0; bt < 2; bt++) {
                int cc = ks * 2 + b_c;
                uint32_t bd = Bsm + (uint32_t)(brow[bt] * ROWB) +
                              ((uint32_t)(cc ^ (brow[bt] & 7)) << 4);
                LDSM4(bfr[2 * bt][0], bfr[2 * bt][1], bfr[2 * bt + 1][0], bfr[2 * bt + 1][1], bd);
            }
#pragma unroll
            for (int mt = 0; mt < 4; mt++)
#pragma unroll
                for (int nt = 0; nt < 4; nt++)
                    mma_fp8(acc[mt][nt], afr[mt], bfr[nt]);
        }

        if (kc + 2 < NC) load_stage(kc + 2, (kc + 2) % NSTAGE);
        asm volatile("cp.async.commit_group;");  // keep group count in sync
    }

    // epilogue: fused dequant, direct coalesced float2 stores
#pragma unroll
    for (int mt = 0; mt < 4; mt++) {
#pragma unroll
        for (int nt = 0; nt < 4; nt++) {
            int r = m0 + warp_m * 64 + mt * 16 + (lid >> 2);
            int c = n0 + warp_n * 32 + nt * 8 + (lid & 3) * 2;
            float2 v0 = {acc[mt][nt][0] * inv, acc[mt][nt][1] * inv};
            float2 v1 = {acc[mt][nt][2] * inv, acc[mt][nt][3] * inv};
            *reinterpret_cast<float2*>(out + (size_t)r * Ndim + c) = v0;
            *reinterpret_cast<float2*>(out + (size_t)(r + 8) * Ndim + c) = v1;
        }
    }
}

// ---------------- launch ------------------------------------------------------
extern "C" void kernel_launch(void* const* d_in, const int* in_sizes, int n_in,
                              void* d_out, int out_size) {
    const float* x = (const float*)d_in[0];
    const float* w = (const float*)d_in[1];
    float* out = (float*)d_out;

    k_reset<<<1, 1>>>();
    k_absmax<<<2048, 256>>>((const float4*)x, Mdim * Kdim / 4, 0);
    k_absmax<<<1024, 256>>>((const float4*)w, Kdim * Ndim / 4, 1);
    k_scales<<<1, 1>>>();
    k_quant_x<<<4096, 256>>>((const float4*)x, Mdim * Kdim / 16);
    k_quant_wt<<<dim3(Ndim / 32, Kdim / 32), dim3(32, 8)>>>(w);

    cudaFuncSetAttribute(k_gemm, cudaFuncAttributeMaxDynamicSharedMemorySize, SMEM_TOTAL);
    k_gemm<<<dim3(Ndim / BN, Mdim / BM), 256, SMEM_TOTAL>>>(out);
}

// round 7
// speedup vs baseline: 1.0336x; 1.0336x over previous
#include <cuda_runtime.h>
#include <cuda_bf16.h>
#include <cuda_fp8.h>
#include <cstdint>

static constexpr int Mdim = 16384;
static constexpr int Kdim = 4096;
static constexpr int Ndim = 4096;
static constexpr float FP8MAX = 448.0f;

// ---------------- scratch (device globals; no dynamic allocation) -------------
__device__ __align__(16) __nv_bfloat16 g_xq[(size_t)Mdim * Kdim];  // quantized x as bf16
__device__ __align__(16) __nv_bfloat16 g_wq[(size_t)Ndim * Kdim];  // quantized w^T as bf16
__device__ unsigned int g_absmax[2];
__device__ float g_scales[3];  // sx, sw, 1/(sx*sw)

// ---------------- phase 1: absmax reductions ---------------------------------
__global__ void k_reset() {
    g_absmax[0] = 0u;
    g_absmax[1] = 0u;
}

__global__ void k_absmax(const float4* __restrict__ p, int n4, int which) {
    float m = 0.f;
    for (int i = blockIdx.x * blockDim.x + threadIdx.x; i < n4; i += gridDim.x * blockDim.x) {
        float4 v = p[i];
        m = fmaxf(m, fmaxf(fmaxf(fabsf(v.x), fabsf(v.y)), fmaxf(fabsf(v.z), fabsf(v.w))));
    }
#pragma unroll
    for (int o = 16; o > 0; o >>= 1) m = fmaxf(m, __shfl_xor_sync(0xffffffffu, m, o));
    __shared__ float red[8];
    if ((threadIdx.x & 31) == 0) red[threadIdx.x >> 5] = m;
    __syncthreads();
    if (threadIdx.x == 0) {
        float mm = red[0];
#pragma unroll
        for (int i = 1; i < 8; i++) mm = fmaxf(mm, red[i]);
        atomicMax(&g_absmax[which], __float_as_uint(mm));
    }
}

__global__ void k_scales() {
    float ax = __uint_as_float(g_absmax[0]);
    float aw = __uint_as_float(g_absmax[1]);
    float sx = FP8MAX / ax;
    float sw = FP8MAX / aw;
    g_scales[0] = sx;
    g_scales[1] = sw;
    g_scales[2] = 1.0f / (sx * sw);
}

// ---------------- phase 2: quantize ------------------------------------------
// float -> (clip, RNE fp8 e4m3 satfinite) -> bf16 (exact re-expansion)
__device__ __forceinline__ unsigned short quant_to_bf16(float v, float s) {
    float q = fminf(fmaxf(v * s, -FP8MAX), FP8MAX);
    __nv_fp8_e4m3 f8(q);                            // RN + satfinite, matches jnp cast
    __nv_bfloat16 b = __float2bfloat16((float)f8);  // exact
    return *reinterpret_cast<unsigned short*>(&b);
}

__global__ void k_quant_x(const float4* __restrict__ x, int n8) {
    const float s = g_scales[0];
    uint4* __restrict__ out = reinterpret_cast<uint4*>(g_xq);
    for (int i = blockIdx.x * blockDim.x + threadIdx.x; i < n8; i += gridDim.x * blockDim.x) {
        float4 a = x[2 * i], b = x[2 * i + 1];
        uint4 r;
        r.x = (unsigned)quant_to_bf16(a.x, s) | ((unsigned)quant_to_bf16(a.y, s) << 16);
        r.y = (unsigned)quant_to_bf16(a.z, s) | ((unsigned)quant_to_bf16(a.w, s) << 16);
        r.z = (unsigned)quant_to_bf16(b.x, s) | ((unsigned)quant_to_bf16(b.y, s) << 16);
        r.w = (unsigned)quant_to_bf16(b.z, s) | ((unsigned)quant_to_bf16(b.w, s) << 16);
        out[i] = r;
    }
}

// w[K,N] -> g_wq[N,K] (quantize + transpose via smem tile)
__global__ void k_quant_wt(const float* __restrict__ w) {
    __shared__ float tile[32][33];
    const float s = g_scales[1];
    int n0 = blockIdx.x * 32, k0 = blockIdx.y * 32;
    int tx = threadIdx.x, ty = threadIdx.y;
#pragma unroll
    for (int j = ty; j < 32; j += 8)
        tile[j][tx] = w[(size_t)(k0 + j) * Ndim + n0 + tx];
    __syncthreads();
    unsigned short* __restrict__ out = reinterpret_cast<unsigned short*>(g_wq);
#pragma unroll
    for (int j = ty; j < 32; j += 8)
        out[(size_t)(n0 + j) * Kdim + k0 + tx] = quant_to_bf16(tile[tx][j], s);
}

// ---------------- phase 3: bf16 mma.sync GEMM --------------------------------
// CTA tile 256x128, BK=64 (128B rows), 8 warps (4x2) each 64x64,
// 3-stage cp.async pipeline, XOR-swizzled smem, fp32 register accumulators.
static constexpr int BM = 256, BN = 128, BK = 64;
static constexpr int ROWB = BK * 2;                 // 128 bytes per smem row
static constexpr int ATILE = BM * ROWB;             // 32768
static constexpr int BTILE = BN * ROWB;             // 16384
static constexpr int STAGE = ATILE + BTILE;         // 49152
static constexpr int NSTAGE = 3;
static constexpr int SMEM_TOTAL = NSTAGE * STAGE;   // 147456

#define CPA16(dst, src) \
    asm volatile("cp.async.cg.shared.global [%0], [%1], 16;" :: "r"(dst), "l"(src))
#define LDSM4(r0, r1, r2, r3, addr) \
    asm volatile("ldmatrix.sync.aligned.m8n8.x4.shared.b16 {%0,%1,%2,%3}, [%4];" \
                 : "=r"(r0), "=r"(r1), "=r"(r2), "=r"(r3) : "r"(addr))

__device__ __forceinline__ void mma_bf16(float* c, const uint32_t* a, const uint32_t* b) {
    asm volatile(
        "mma.sync.aligned.m16n8k16.row.col.f32.bf16.bf16.f32 "
        "{%0,%1,%2,%3}, {%4,%5,%6,%7}, {%8,%9}, {%0,%1,%2,%3};"
        : "+f"(c[0]), "+f"(c[1]), "+f"(c[2]), "+f"(c[3])
        : "r"(a[0]), "r"(a[1]), "r"(a[2]), "r"(a[3]), "r"(b[0]), "r"(b[1]));
}

__global__ void __launch_bounds__(256, 1) k_gemm(float* __restrict__ out) {
    extern __shared__ char smem[];
    const uint32_t sb = (uint32_t)__cvta_generic_to_shared(smem);
    const int tid = threadIdx.x, wid = tid >> 5, lid = tid & 31;
    const int warp_m = wid >> 1, warp_n = wid & 1;   // 4 x 2 warps, each 64x64
    const int n0 = blockIdx.x * BN, m0 = blockIdx.y * BM;
    const float inv = g_scales[2];

    const char* Ag = (const char*)(g_xq + (size_t)m0 * Kdim);
    const char* Bg = (const char*)(g_wq + (size_t)n0 * Kdim);

    const int lr = tid >> 3;          // 0..31 base row
    const int lc = tid & 7;           // 16B chunk within 128B row

    auto load_stage = [&](int kc, int st) {
        const uint32_t ab = sb + st * STAGE;
        const uint32_t bb = ab + ATILE;
        const size_t kbyte = (size_t)kc * ROWB;
#pragma unroll
        for (int i = 0; i < 8; i++) {  // A: 256 rows
            int r = lr + i * 32;
            uint32_t so = (uint32_t)(r * ROWB) + ((uint32_t)(lc ^ (r & 7)) << 4);
            CPA16(ab + so, Ag + (size_t)r * (Kdim * 2) + kbyte + lc * 16);
        }
#pragma unroll
        for (int i = 0; i < 4; i++) {  // B: 128 rows
            int r = lr + i * 32;
            uint32_t so = (uint32_t)(r * ROWB) + ((uint32_t)(lc ^ (r & 7)) << 4);
            CPA16(bb + so, Bg + (size_t)r * (Kdim * 2) + kbyte + lc * 16);
        }
    };

    // ldmatrix per-thread row/chunk layout
    int arow[4], brow[4];
#pragma unroll
    for (int mt = 0; mt < 4; mt++) arow[mt] = warp_m * 64 + mt * 16 + (lid & 15);
#pragma unroll
    for (int bt = 0; bt < 4; bt++) brow[bt] = warp_n * 64 + bt * 16 + ((lid >> 4) << 3) + (lid & 7);
    const int a_c = lid >> 4;          // low/high 16B of the k16 slice
    const int b_c = (lid >> 3) & 1;

    float acc[4][8][4];
#pragma unroll
    for (int mt = 0; mt < 4; mt++)
#pragma unroll
        for (int nt = 0; nt < 8; nt++)
#pragma unroll
            for (int i = 0; i < 4; i++) acc[mt][nt][i] = 0.f;

    load_stage(0, 0);
    asm volatile("cp.async.commit_group;");
    load_stage(1, 1);
    asm volatile("cp.async.commit_group;");

    const int NC = Kdim / BK;  // 64
    for (int kc = 0; kc < NC; kc++) {
        asm volatile("cp.async.wait_group 1;");
        __syncthreads();
        const int st = kc % NSTAGE;
        const uint32_t Asm = sb + st * STAGE;
        const uint32_t Bsm = Asm + ATILE;

#pragma unroll
        for (int ks = 0; ks < 4; ks++) {  // 4 x k16 per 128B row
            uint32_t afr[4][4], bfr[8][2];
#pragma unroll
            for (int mt = 0; mt < 4; mt++) {
                int cc = ks * 2 + a_c;
                uint32_t ad = Asm + (uint32_t)(arow[mt] * ROWB) +
                              ((uint32_t)(cc ^ (arow[mt] & 7)) << 4);
                LDSM4(afr[mt][0], afr[mt][1], afr[mt][2], afr[mt][3], ad);
            }
#pragma unroll
            for (int bt = 0; bt < 4; bt++) {
                int cc = ks * 2 + b_c;
                uint32_t bd = Bsm + (uint32_t)(brow[bt] * ROWB) +
                              ((uint32_t)(cc ^ (brow[bt] & 7)) << 4);
                LDSM4(bfr[2 * bt][0], bfr[2 * bt][1], bfr[2 * bt + 1][0], bfr[2 * bt + 1][1], bd);
            }
#pragma unroll
            for (int mt = 0; mt < 4; mt++)
#pragma unroll
                for (int nt = 0; nt < 8; nt++)
                    mma_bf16(acc[mt][nt], afr[mt], bfr[nt]);
        }

        if (kc + 2 < NC) load_stage(kc + 2, (kc + 2) % NSTAGE);
        asm volatile("cp.async.commit_group;");  // keep group count in sync
    }

    // epilogue: fused dequant, direct coalesced float2 stores
#pragma unroll
    for (int mt = 0; mt < 4; mt++) {
#pragma unroll
        for (int nt = 0; nt < 8; nt++) {
            int r = m0 + warp_m * 64 + mt * 16 + (lid >> 2);
            int c = n0 + warp_n * 64 + nt * 8 + (lid & 3) * 2;
            float2 v0 = {acc[mt][nt][0] * inv, acc[mt][nt][1] * inv};
            float2 v1 = {acc[mt][nt][2] * inv, acc[mt][nt][3] * inv};
            *reinterpret_cast<float2*>(out + (size_t)r * Ndim + c) = v0;
            *reinterpret_cast<float2*>(out + (size_t)(r + 8) * Ndim + c) = v1;
        }
    }
}

// ---------------- launch ------------------------------------------------------
extern "C" void kernel_launch(void* const* d_in, const int* in_sizes, int n_in,
                              void* d_out, int out_size) {
    const float* x = (const float*)d_in[0];
    const float* w = (const float*)d_in[1];
    float* out = (float*)d_out;

    k_reset<<<1, 1>>>();
    k_absmax<<<2048, 256>>>((const float4*)x, Mdim * Kdim / 4, 0);
    k_absmax<<<1024, 256>>>((const float4*)w, Kdim * Ndim / 4, 1);
    k_scales<<<1, 1>>>();
    k_quant_x<<<4096, 256>>>((const float4*)x, Mdim * Kdim / 8);
    k_quant_wt<<<dim3(Ndim / 32, Kdim / 32), dim3(32, 8)>>>(w);

    cudaFuncSetAttribute(k_gemm, cudaFuncAttributeMaxDynamicSharedMemorySize, SMEM_TOTAL);
    k_gemm<<<dim3(Ndim / BN, Mdim / BM), 256, SMEM_TOTAL>>>(out);
}

// round 9
// speedup vs baseline: 1.1730x; 1.1349x over previous
#include <cuda_runtime.h>
#include <cuda_bf16.h>
#include <cuda_fp8.h>
#include <cstdint>

static constexpr int Mdim = 16384;
static constexpr int Kdim = 4096;
static constexpr int Ndim = 4096;
static constexpr float FP8MAX = 448.0f;

// ---------------- scratch (device globals; no dynamic allocation) -------------
__device__ __align__(16) __nv_bfloat16 g_xq[(size_t)Mdim * Kdim];  // quantized x as bf16
__device__ __align__(16) __nv_bfloat16 g_wq[(size_t)Ndim * Kdim];  // quantized w^T as bf16
__device__ unsigned int g_absmax[2];
__device__ float g_scales[3];  // sx, sw, 1/(sx*sw)

// ---------------- phase 1: absmax reductions ---------------------------------
__global__ void k_reset() {
    g_absmax[0] = 0u;
    g_absmax[1] = 0u;
}

__global__ void k_absmax(const float4* __restrict__ p, int n4, int which) {
    float m = 0.f;
    for (int i = blockIdx.x * blockDim.x + threadIdx.x; i < n4; i += gridDim.x * blockDim.x) {
        float4 v = p[i];
        m = fmaxf(m, fmaxf(fmaxf(fabsf(v.x), fabsf(v.y)), fmaxf(fabsf(v.z), fabsf(v.w))));
    }
#pragma unroll
    for (int o = 16; o > 0; o >>= 1) m = fmaxf(m, __shfl_xor_sync(0xffffffffu, m, o));
    __shared__ float red[8];
    if ((threadIdx.x & 31) == 0) red[threadIdx.x >> 5] = m;
    __syncthreads();
    if (threadIdx.x == 0) {
        float mm = red[0];
#pragma unroll
        for (int i = 1; i < 8; i++) mm = fmaxf(mm, red[i]);
        atomicMax(&g_absmax[which], __float_as_uint(mm));
    }
}

__global__ void k_scales() {
    float ax = __uint_as_float(g_absmax[0]);
    float aw = __uint_as_float(g_absmax[1]);
    float sx = FP8MAX / ax;
    float sw = FP8MAX / aw;
    g_scales[0] = sx;
    g_scales[1] = sw;
    g_scales[2] = 1.0f / (sx * sw);
}

// ---------------- phase 2: quantize ------------------------------------------
// float -> (clip, RNE fp8 e4m3 satfinite) -> bf16 (exact re-expansion)
__device__ __forceinline__ unsigned short quant_to_bf16(float v, float s) {
    float q = fminf(fmaxf(v * s, -FP8MAX), FP8MAX);
    __nv_fp8_e4m3 f8(q);                            // RN + satfinite, matches jnp cast
    __nv_bfloat16 b = __float2bfloat16((float)f8);  // exact
    return *reinterpret_cast<unsigned short*>(&b);
}

__global__ void k_quant_x(const float4* __restrict__ x, int n8) {
    const float s = g_scales[0];
    uint4* __restrict__ out = reinterpret_cast<uint4*>(g_xq);
    for (int i = blockIdx.x * blockDim.x + threadIdx.x; i < n8; i += gridDim.x * blockDim.x) {
        float4 a = x[2 * i], b = x[2 * i + 1];
        uint4 r;
        r.x = (unsigned)quant_to_bf16(a.x, s) | ((unsigned)quant_to_bf16(a.y, s) << 16);
        r.y = (unsigned)quant_to_bf16(a.z, s) | ((unsigned)quant_to_bf16(a.w, s) << 16);
        r.z = (unsigned)quant_to_bf16(b.x, s) | ((unsigned)quant_to_bf16(b.y, s) << 16);
        r.w = (unsigned)quant_to_bf16(b.z, s) | ((unsigned)quant_to_bf16(b.w, s) << 16);
        out[i] = r;
    }
}

// w[K,N] -> g_wq[N,K] (quantize + transpose via smem tile)
__global__ void k_quant_wt(const float* __restrict__ w) {
    __shared__ float tile[32][33];
    const float s = g_scales[1];
    int n0 = blockIdx.x * 32, k0 = blockIdx.y * 32;
    int tx = threadIdx.x, ty = threadIdx.y;
#pragma unroll
    for (int j = ty; j < 32; j += 8)
        tile[j][tx] = w[(size_t)(k0 + j) * Ndim + n0 + tx];
    __syncthreads();
    unsigned short* __restrict__ out = reinterpret_cast<unsigned short*>(g_wq);
#pragma unroll
    for (int j = ty; j < 32; j += 8)
        out[(size_t)(n0 + j) * Kdim + k0 + tx] = quant_to_bf16(tile[tx][j], s);
}

// ---------------- phase 3: bf16 mma.sync GEMM --------------------------------
// CTA tile 128x128, BK=64 (128B rows), 4 warps (2x2) each 64x64,
// 3-stage cp.async pipeline, XOR-swizzled smem, fp32 register accumulators,
// 2 CTAs/SM for latency overlap.
static constexpr int BM = 128, BN = 128, BK = 64;
static constexpr int ROWB = BK * 2;                 // 128 bytes per smem row
static constexpr int ATILE = BM * ROWB;             // 16384
static constexpr int STAGE = 2 * ATILE;             // A + B = 32768
static constexpr int NSTAGE = 3;
static constexpr int SMEM_TOTAL = NSTAGE * STAGE;   // 98304

#define CPA16(dst, src) \
    asm volatile("cp.async.cg.shared.global [%0], [%1], 16;" :: "r"(dst), "l"(src))
#define LDSM4(r0, r1, r2, r3, addr) \
    asm volatile("ldmatrix.sync.aligned.m8n8.x4.shared.b16 {%0,%1,%2,%3}, [%4];" \
                 : "=r"(r0), "=r"(r1), "=r"(r2), "=r"(r3) : "r"(addr))

__device__ __forceinline__ void mma_bf16(float* c, const uint32_t* a, const uint32_t* b) {
    asm volatile(
        "mma.sync.aligned.m16n8k16.row.col.f32.bf16.bf16.f32 "
        "{%0,%1,%2,%3}, {%4,%5,%6,%7}, {%8,%9}, {%0,%1,%2,%3};"
        : "+f"(c[0]), "+f"(c[1]), "+f"(c[2]), "+f"(c[3])
        : "r"(a[0]), "r"(a[1]), "r"(a[2]), "r"(a[3]), "r"(b[0]), "r"(b[1]));
}

__global__ void __launch_bounds__(128, 2) k_gemm(float* __restrict__ out) {
    extern __shared__ char smem[];
    const uint32_t sb = (uint32_t)__cvta_generic_to_shared(smem);
    const int tid = threadIdx.x, wid = tid >> 5, lid = tid & 31;
    const int warp_m = wid >> 1, warp_n = wid & 1;   // 2 x 2 warps, each 64x64
    const int n0 = blockIdx.x * BN, m0 = blockIdx.y * BM;
    const float inv = g_scales[2];

    const char* Ag = (const char*)(g_xq + (size_t)m0 * Kdim);
    const char* Bg = (const char*)(g_wq + (size_t)n0 * Kdim);

    const int lr = tid >> 3;          // 0..15 base row
    const int lc = tid & 7;           // 16B chunk within 128B row

    auto load_stage = [&](int kc, int st) {
        const uint32_t ab = sb + st * STAGE;
        const uint32_t bb = ab + ATILE;
        const size_t kbyte = (size_t)kc * ROWB;
#pragma unroll
        for (int i = 0; i < 8; i++) {  // A: 128 rows, 16 rows/iter
            int r = lr + i * 16;
            uint32_t so = (uint32_t)(r * ROWB) + ((uint32_t)(lc ^ (r & 7)) << 4);
            CPA16(ab + so, Ag + (size_t)r * (Kdim * 2) + kbyte + lc * 16);
        }
#pragma unroll
        for (int i = 0; i < 8; i++) {  // B: 128 rows
            int r = lr + i * 16;
            uint32_t so = (uint32_t)(r * ROWB) + ((uint32_t)(lc ^ (r & 7)) << 4);
            CPA16(bb + so, Bg + (size_t)r * (Kdim * 2) + kbyte + lc * 16);
        }
    };

    // ldmatrix per-thread row/chunk layout
    int arow[4], brow[4];
#pragma unroll
    for (int mt = 0; mt < 4; mt++) arow[mt] = warp_m * 64 + mt * 16 + (lid & 15);
#pragma unroll
    for (int bt = 0; bt < 4; bt++) brow[bt] = warp_n * 64 + bt * 16 + ((lid >> 4) << 3) + (lid & 7);
    const int a_c = lid >> 4;          // low/high 16B of the k16 slice
    const int b_c = (lid >> 3) & 1;

    float acc[4][8][4];
#pragma unroll
    for (int mt = 0; mt < 4; mt++)
#pragma unroll
        for (int nt = 0; nt < 8; nt++)
#pragma unroll
            for (int i = 0; i < 4; i++) acc[mt][nt][i] = 0.f;

    load_stage(0, 0);
    asm volatile("cp.async.commit_group;");
    load_stage(1, 1);
    asm volatile("cp.async.commit_group;");

    const int NC = Kdim / BK;  // 64
    for (int kc = 0; kc < NC; kc++) {
        asm volatile("cp.async.wait_group 1;");
        __syncthreads();
        const int st = kc % NSTAGE;
        const uint32_t Asm = sb + st * STAGE;
        const uint32_t Bsm = Asm + ATILE;

#pragma unroll
        for (int ks = 0; ks < 4; ks++) {  // 4 x k16 per 128B row
            uint32_t afr[4][4], bfr[8][2];
#pragma unroll
            for (int mt = 0; mt < 4; mt++) {
                int cc = ks * 2 + a_c;
                uint32_t ad = Asm + (uint32_t)(arow[mt] * ROWB) +
                              ((uint32_t)(cc ^ (arow[mt] & 7)) << 4);
                LDSM4(afr[mt][0], afr[mt][1], afr[mt][2], afr[mt][3], ad);
            }
#pragma unroll
            for (int bt = 0; bt < 4; bt++) {
                int cc = ks * 2 + b_c;
                uint32_t bd = Bsm + (uint32_t)(brow[bt] * ROWB) +
                              ((uint32_t)(cc ^ (brow[bt] & 7)) << 4);
                LDSM4(bfr[2 * bt][0], bfr[2 * bt][1], bfr[2 * bt + 1][0], bfr[2 * bt + 1][1], bd);
            }
#pragma unroll
            for (int mt = 0; mt < 4; mt++)
#pragma unroll
                for (int nt = 0; nt < 8; nt++)
                    mma_bf16(acc[mt][nt], afr[mt], bfr[nt]);
        }

        if (kc + 2 < NC) load_stage(kc + 2, (kc + 2) % NSTAGE);
        asm volatile("cp.async.commit_group;");  // keep group count in sync
    }

    // epilogue: fused dequant, direct coalesced float2 stores
#pragma unroll
    for (int mt = 0; mt < 4; mt++) {
#pragma unroll
        for (int nt = 0; nt < 8; nt++) {
            int r = m0 + warp_m * 64 + mt * 16 + (lid >> 2);
            int c = n0 + warp_n * 64 + nt * 8 + (lid & 3) * 2;
            float2 v0 = {acc[mt][nt][0] * inv, acc[mt][nt][1] * inv};
            float2 v1 = {acc[mt][nt][2] * inv, acc[mt][nt][3] * inv};
            *reinterpret_cast<float2*>(out + (size_t)r * Ndim + c) = v0;
            *reinterpret_cast<float2*>(out + (size_t)(r + 8) * Ndim + c) = v1;
        }
    }
}

// ---------------- launch ------------------------------------------------------
extern "C" void kernel_launch(void* const* d_in, const int* in_sizes, int n_in,
                              void* d_out, int out_size) {
    const float* x = (const float*)d_in[0];
    const float* w = (const float*)d_in[1];
    float* out = (float*)d_out;

    k_reset<<<1, 1>>>();
    k_absmax<<<2048, 256>>>((const float4*)x, Mdim * Kdim / 4, 0);
    k_absmax<<<1024, 256>>>((const float4*)w, Kdim * Ndim / 4, 1);
    k_scales<<<1, 1>>>();
    k_quant_x<<<4096, 256>>>((const float4*)x, Mdim * Kdim / 8);
    k_quant_wt<<<dim3(Ndim / 32, Kdim / 32), dim3(32, 8)>>>(w);

    cudaFuncSetAttribute(k_gemm, cudaFuncAttributeMaxDynamicSharedMemorySize, SMEM_TOTAL);
    k_gemm<<<dim3(Ndim / BN, Mdim / BM), 128, SMEM_TOTAL>>>(out);
}